// round 17
// baseline (speedup 1.0000x reference)
#include <cuda_runtime.h>
#include <math.h>

// Fixed shapes: B=32, S=128, V=8, T=66 -> 256 independent sequences.
// One block (64 thr) per TWO sequences; each warp runs TWO same-direction
// chains (E registers shared):
//   warp 0: forward  alpha chains of seqA and seqB
//   warp 1: backward w     chains of seqA and seqB
// u pairs 0..31 via smem broadcast LDS; pair 32 register-resident.
// Warp-synchronous (no barrier in loop). Meet once per seq: Z = (a63 M).w64.
#define TT   66
#define SS   128
#define NSEQ 256
#define NBLK 128
#define NTHR 64
#define USTR 72

typedef unsigned long long ull;

__device__ float        g_partial[NSEQ];
__device__ unsigned int g_count = 0;

static __device__ __forceinline__ ull pk2(float lo, float hi) {
    ull r; asm("mov.b64 %0, {%1,%2};" : "=l"(r) : "f"(lo), "f"(hi)); return r;
}
static __device__ __forceinline__ void fma2(ull& d, ull a, ull b) {
    asm("fma.rn.f32x2 %0, %1, %2, %0;" : "+l"(d) : "l"(a), "l"(b));
}
static __device__ __forceinline__ void add2(ull& d, ull a, ull b) {
    asm("add.rn.f32x2 %0, %1, %2;" : "=l"(d) : "l"(a), "l"(b));
}
static __device__ __forceinline__ float2 upk2(ull v) {
    float lo, hi; asm("mov.b64 {%0,%1}, %2;" : "=f"(lo), "=f"(hi) : "l"(v));
    return make_float2(lo, hi);
}
#define CFENCE() asm volatile("" ::: "memory")

// smem floats: esh 2*SS*TT + ubuf 8*USTR + wslab 2*68 + sL4 sSc2 sgold4 sws2 wred2 + flag
#define SMEM_FLOATS (2*SS*TT + 8*USTR + 2*68 + 16)
#define SMEM_BYTES  (SMEM_FLOATS*4)

__global__ void __launch_bounds__(NTHR, 1) crf_kernel(
    const float* __restrict__ score,       // [B,S,S,T]
    const float* __restrict__ trans,       // [T,T]
    const float* __restrict__ startT,      // [T]
    const float* __restrict__ endT,        // [T]
    const int*   __restrict__ v_label,     // [B*V]
    const int*   __restrict__ role_label,  // [B*V][S]
    float*       __restrict__ out)
{
    extern __shared__ __align__(16) float sm[];
    float* esh   = sm;                     // [2 seq][SS*TT] exp(emissions)
    float* ubuf  = esh + 2*SS*TT;          // [(w*2+p)*2+pp][USTR]
    float* wslab = ubuf + 8*USTR;          // [2 seq][68] backward finals (raw)
    float* sL    = wslab + 2*68;           // [w*2+p]
    float* sSc   = sL + 4;                 // [p] backward pending scale
    float* sgold = sSc + 2;                // [w*2+p]
    float* swsum = sgold + 4;              // [p]
    float* wred  = swsum + 2;              // [2]
    int*   sflag = (int*)(wred + 2);

    const int tid  = threadIdx.x;
    const int lane = tid & 31;
    const int w    = tid >> 5;             // direction: 0 = fwd, 1 = bwd
    const int sA   = blockIdx.x*2;
    const float* erowA = score + ((size_t)((sA >> 3)*SS + __ldg(&v_label[sA])))*SS*TT;
    const float* erowB = score + ((size_t)(((sA+1) >> 3)*SS + __ldg(&v_label[sA+1])))*SS*TT;

    #define SLAB(p, pp) (ubuf + ((w*2 + (p))*2 + (pp))*USTR)

    // ---- gold paths: thread covers positions tid, tid+64 of each seq ----
    #pragma unroll
    for (int p = 0; p < 2; p++) {
        const float* er = p ? erowB : erowA;
        int seq = sA + p;
        float gold = 0.f;
        #pragma unroll
        for (int q = 0; q < 2; q++) {
            int s  = tid + 64*q;
            int tg = __ldg(&role_label[seq*SS + s]);
            float gg = __ldg(&er[s*TT + tg]);
            if (s < SS-1) gg += __ldg(&trans[tg*TT + __ldg(&role_label[seq*SS + s + 1])]);
            else          gg += __ldg(&endT[tg]);
            if (s == 0)   gg += __ldg(&startT[tg]);
            gold += gg;
        }
        #pragma unroll
        for (int o = 16; o; o >>= 1) gold += __shfl_xor_sync(~0u, gold, o);
        if (lane == 0) sgold[w*2 + p] = gold;
    }

    // ---- stage exp(emissions) for both sequences (all 64 threads) ----
    {
        const float4* srcA = (const float4*)erowA;
        const float4* srcB = (const float4*)erowB;
        float4* dstA = (float4*)esh;
        float4* dstB = (float4*)(esh + SS*TT);
        #pragma unroll 3
        for (int k = tid; k < (SS*TT)/4; k += NTHR) {
            float4 va = __ldg(&srcA[k]);
            float4 vb = __ldg(&srcB[k]);
            va.x = __expf(va.x); va.y = __expf(va.y); va.z = __expf(va.z); va.w = __expf(va.w);
            vb.x = __expf(vb.x); vb.y = __expf(vb.y); vb.z = __expf(vb.z); vb.w = __expf(vb.w);
            dstA[k] = va;
            dstB[k] = vb;
        }
    }

    // ---- E registers (dual-interleave); direction per warp; SHARED by chains ----
    ull eA[33], eB[33], xA[4], xB[4];
    float cx0, cx1, cy0, cy1;
    const int g = lane & 7;
    if (w == 0) {
        #pragma unroll
        for (int m = 0; m < 33; m++) {
            float2 f0 = __ldg((const float2*)(trans + (2*m  )*TT) + lane);
            float2 f1 = __ldg((const float2*)(trans + (2*m+1)*TT) + lane);
            float a = __expf(f0.x), bq = __expf(f0.y);
            float c = __expf(f1.x), d  = __expf(f1.y);
            eA[m] = pk2(a, d);
            eB[m] = pk2(bq, c);
        }
        #pragma unroll
        for (int q = 0; q < 4; q++) {
            int rr = 2*(4*g + q);
            float2 h0 = __ldg((const float2*)(trans + rr*TT + 64));
            float2 h1 = __ldg((const float2*)(trans + (rr+1)*TT + 64));
            xA[q] = pk2(__expf(h0.x), __expf(h1.y));
            xB[q] = pk2(__expf(h0.y), __expf(h1.x));
        }
        float2 k0 = __ldg((const float2*)(trans + 64*TT + 64));
        float2 k1 = __ldg((const float2*)(trans + 65*TT + 64));
        cx0 = __expf(k0.x); cx1 = __expf(k1.x);
        cy0 = __expf(k0.y); cy1 = __expf(k1.y);
    } else {
        const float* row0 = trans + (2*lane    )*TT;
        const float* row1 = trans + (2*lane + 1)*TT;
        #pragma unroll
        for (int m = 0; m < 33; m++) {
            float2 f0 = __ldg((const float2*)row0 + m);
            float2 f1 = __ldg((const float2*)row1 + m);
            float a = __expf(f0.x), bq = __expf(f0.y);
            float c = __expf(f1.x), d  = __expf(f1.y);
            eA[m] = pk2(a, d);
            eB[m] = pk2(c, bq);
        }
        #pragma unroll
        for (int q = 0; q < 4; q++) {
            int rr = 2*(4*g + q);
            float2 h0 = __ldg((const float2*)(trans + 64*TT + rr));
            float2 h1 = __ldg((const float2*)(trans + 65*TT + rr));
            xA[q] = pk2(__expf(h0.x), __expf(h1.y));
            xB[q] = pk2(__expf(h1.x), __expf(h0.y));
        }
        float2 k0 = __ldg((const float2*)(trans + 64*TT + 64));
        float2 k1 = __ldg((const float2*)(trans + 65*TT + 64));
        cx0 = __expf(k0.x); cx1 = __expf(k0.y);
        cy0 = __expf(k1.x); cy1 = __expf(k1.y);
    }

    float2 bc = w ? __ldg((const float2*)endT + lane) : __ldg((const float2*)startT + lane);
    float2 bx = w ? __ldg((const float2*)(endT + 64)) : __ldg((const float2*)(startT + 64));
    float ebcx = __expf(bc.x), ebcy = __expf(bc.y);
    float ebxx = __expf(bx.x), ebxy = __expf(bx.y);

    __syncthreads();   // esh staged by both warps

    // ---- init both chains of this warp ----
    const float* eA0 = esh + (w ? 127*TT : 0);
    const float* eB0 = esh + SS*TT + (w ? 127*TT : 0);
    float rA0 = ebcx * eA0[2*lane],     rA1 = ebcy * eA0[2*lane + 1];
    float xA64 = ebxx * eA0[64],        xA65 = ebxy * eA0[65];
    float rB0 = ebcx * eB0[2*lane],     rB1 = ebcy * eB0[2*lane + 1];
    float xB64 = ebxx * eB0[64],        xB65 = ebxy * eB0[65];

    float* ucA = SLAB(0,0); float* unA = SLAB(0,1);
    float* ucB = SLAB(1,0); float* unB = SLAB(1,1);
    ((float2*)ucA)[lane] = make_float2(rA0, rA1);
    ((float2*)ucB)[lane] = make_float2(rB0, rB1);

    float mA = fmaxf(fmaxf(rA0, rA1), fmaxf(xA64, xA65));
    float mB = fmaxf(fmaxf(rB0, rB1), fmaxf(xB64, xB65));
    #pragma unroll
    for (int o = 16; o; o >>= 1) {
        mA = fmaxf(mA, __shfl_xor_sync(~0u, mA, o));
        mB = fmaxf(mB, __shfl_xor_sync(~0u, mB, o));
    }
    float scA = __fdividef(1.0f, mA);
    float scB = __fdividef(1.0f, mB);
    float LA  = __logf(mA);
    float LB  = __logf(mB);
    __syncwarp();

    const int dE = w ? -TT : TT;
    const float* emAq = esh + (w ? 126*TT : TT);
    const float* emBq = esh + SS*TT + (w ? 126*TT : TT);

    // ---- one chain-step (R12 body); called for each chain per interval ----
    auto STEP1 = [&](const float* uc, float* un, const float* emrow, float scl,
                     float& r0, float& r1, float& x64v, float& x65v) {
        float2 em  = ((const float2*)emrow)[lane];
        float2 emx = *(const float2*)(emrow + 64);
        ull x01 = pk2(x64v, x65v);
        const ulonglong2* ux = (const ulonglong2*)(uc + 8*g);
        ulonglong2 va0 = ux[0], va1 = ux[1];
        ull XA = 0, XB = 0;
        fma2(XA, va0.x, xA[0]); fma2(XB, va0.x, xB[0]);
        fma2(XA, va0.y, xA[1]); fma2(XB, va0.y, xB[1]);
        fma2(XA, va1.x, xA[2]); fma2(XB, va1.x, xB[2]);
        fma2(XA, va1.y, xA[3]); fma2(XB, va1.y, xB[3]);
        float2 fa = upk2(XA), fb = upk2(XB);
        float px = fa.x + fb.y;
        float py = fa.y + fb.x;
        px += __shfl_xor_sync(~0u, px, 1);  py += __shfl_xor_sync(~0u, py, 1);
        px += __shfl_xor_sync(~0u, px, 2);  py += __shfl_xor_sync(~0u, py, 2);
        px += __shfl_xor_sync(~0u, px, 4);  py += __shfl_xor_sync(~0u, py, 4);
        px += x64v*cx0 + x65v*cx1;
        py += x64v*cy0 + x65v*cy1;
        const ulonglong2* up = (const ulonglong2*)uc;
        ull dA0 = 0, dA1 = 0, dB0 = 0, dB1 = 0;
        #pragma unroll
        for (int i = 0; i < 16; i++) {
            ulonglong2 va = up[i];
            fma2(dA0, va.x, eA[2*i]);   fma2(dB0, va.x, eB[2*i]);
            fma2(dA1, va.y, eA[2*i+1]); fma2(dB1, va.y, eB[2*i+1]);
        }
        fma2(dA0, x01, eA[32]);
        fma2(dB0, x01, eB[32]);
        add2(dA0, dA0, dA1); add2(dB0, dB0, dB1);
        float2 A = upk2(dA0), Bv = upk2(dB0);
        r0   = (A.x + Bv.y) * (scl * em.x);
        r1   = (A.y + Bv.x) * (scl * em.y);
        x64v = px * (scl * emx.x);
        x65v = py * (scl * emx.y);
        CFENCE();
        ((float2*)un)[lane] = make_float2(r0, r1);
        CFENCE();
    };

    // ---- 63 intervals: each advances BOTH sequences; renorm every 8 ----
    for (int grp = 0; grp < 8; grp++) {
        const int n = (grp == 7) ? 7 : 8;
        #pragma unroll 8
        for (int q = 0; q < n; q++) {
            float sa = (q == 0) ? scA : 1.0f;
            float sb = (q == 0) ? scB : 1.0f;
            STEP1(ucA, unA, emAq, sa, rA0, rA1, xA64, xA65);
            STEP1(ucB, unB, emBq, sb, rB0, rB1, xB64, xB65);
            float* tp;
            tp = ucA; ucA = unA; unA = tp;
            tp = ucB; ucB = unB; unB = tp;
            emAq += dE; emBq += dE;
        }
        if (grp < 7) {
            mA = fmaxf(fmaxf(rA0, rA1), fmaxf(xA64, xA65));
            mB = fmaxf(fmaxf(rB0, rB1), fmaxf(xB64, xB65));
            #pragma unroll
            for (int o = 16; o; o >>= 1) {
                mA = fmaxf(mA, __shfl_xor_sync(~0u, mA, o));
                mB = fmaxf(mB, __shfl_xor_sync(~0u, mB, o));
            }
            scA = __fdividef(1.0f, mA);
            scB = __fdividef(1.0f, mB);
            LA += __logf(mA);
            LB += __logf(mB);
        } else { scA = 1.0f; scB = 1.0f; }
    }
    // invariant: actual = stored * exp(L)   (no pending scale after last group)

    // ---- chains meet: backward warp publishes w_64 (raw) per seq ----
    if (w == 1) {
        ((float2*)(wslab))[lane]      = make_float2(rA0, rA1);
        ((float2*)(wslab + 68))[lane] = make_float2(rB0, rB1);
        if (lane == 0) {
            *(float2*)(wslab + 64)      = make_float2(xA64, xA65);
            *(float2*)(wslab + 68 + 64) = make_float2(xB64, xB65);
        }
    }
    if (lane == 0) { sL[w*2 + 0] = LA; sL[w*2 + 1] = LB; }
    __syncthreads();

    // ---- epilogue (forward warp): Z_p = sum_j (alpha_63 M)[j] * w_64[j] ----
    if (w == 0) {
        #pragma unroll
        for (int p = 0; p < 2; p++) {
            const float* ua = (p == 0) ? ucA : ucB;
            const float* uw = wslab + p*68;
            float x64v = (p == 0) ? xA64 : xB64;
            float x65v = (p == 0) ? xA65 : xB65;
            ull x01 = pk2(x64v, x65v);
            const ulonglong2* ux = (const ulonglong2*)(ua + 8*g);
            ulonglong2 va0 = ux[0], va1 = ux[1];
            ull XA = 0, XB = 0;
            fma2(XA, va0.x, xA[0]); fma2(XB, va0.x, xB[0]);
            fma2(XA, va0.y, xA[1]); fma2(XB, va0.y, xB[1]);
            fma2(XA, va1.x, xA[2]); fma2(XB, va1.x, xB[2]);
            fma2(XA, va1.y, xA[3]); fma2(XB, va1.y, xB[3]);
            float2 fa = upk2(XA), fb = upk2(XB);
            float px = fa.x + fb.y;
            float py = fa.y + fb.x;
            px += __shfl_xor_sync(~0u, px, 1);  py += __shfl_xor_sync(~0u, py, 1);
            px += __shfl_xor_sync(~0u, px, 2);  py += __shfl_xor_sync(~0u, py, 2);
            px += __shfl_xor_sync(~0u, px, 4);  py += __shfl_xor_sync(~0u, py, 4);
            px += x64v*cx0 + x65v*cx1;
            py += x64v*cy0 + x65v*cy1;
            const ulonglong2* up = (const ulonglong2*)ua;
            ull dA0 = 0, dA1 = 0, dB0 = 0, dB1 = 0;
            #pragma unroll
            for (int i = 0; i < 16; i++) {
                ulonglong2 va = up[i];
                fma2(dA0, va.x, eA[2*i]);   fma2(dB0, va.x, eB[2*i]);
                fma2(dA1, va.y, eA[2*i+1]); fma2(dB1, va.y, eB[2*i+1]);
            }
            fma2(dA0, x01, eA[32]);
            fma2(dB0, x01, eB[32]);
            add2(dA0, dA0, dA1); add2(dB0, dB0, dB1);
            float2 A = upk2(dA0), Bv = upk2(dB0);
            float2 wv = ((const float2*)uw)[lane];
            float contrib = (A.x + Bv.y) * wv.x + (A.y + Bv.x) * wv.y;
            if (lane == 0) contrib += px*uw[64] + py*uw[65];
            #pragma unroll
            for (int o = 16; o; o >>= 1) contrib += __shfl_xor_sync(~0u, contrib, o);
            if (lane == 0) swsum[p] = contrib;
        }
    }
    __syncthreads();

    if (tid < 2) {
        int p = tid;
        float logZ = __logf(swsum[p]) + sL[0*2 + p] + sL[1*2 + p];
        __stcg(&g_partial[sA + p], logZ - (sgold[0*2 + p] + sgold[1*2 + p]));
    }
    __threadfence();
    __syncthreads();
    if (tid == 0) {
        unsigned c0 = atomicAdd(&g_count, 1u);
        *sflag = (c0 == NBLK - 1) ? 1 : 0;
    }
    __syncthreads();

    // ---- fused final reduction in the last block ----
    if (*sflag) {
        float v = 0.f;
        #pragma unroll
        for (int p = 0; p < 4; p++) v += __ldcg(&g_partial[tid + 64*p]);
        #pragma unroll
        for (int o = 16; o; o >>= 1) v += __shfl_xor_sync(~0u, v, o);
        if (lane == 0) wred[w] = v;
        __syncthreads();
        if (tid == 0) {
            out[0] = (wred[0] + wred[1]) * (1.0f / (float)NSEQ);
            g_count = 0;                   // reset for next graph replay
        }
    }
}

extern "C" void kernel_launch(void* const* d_in, const int* in_sizes, int n_in,
                              void* d_out, int out_size) {
    const float* score      = (const float*)d_in[0];
    const float* trans      = (const float*)d_in[1];
    const float* startT     = (const float*)d_in[2];
    const float* endT       = (const float*)d_in[3];
    const int*   v_label    = (const int*)d_in[4];
    const int*   role_label = (const int*)d_in[5];
    float* out = (float*)d_out;

    cudaFuncSetAttribute(crf_kernel,
                         cudaFuncAttributeMaxDynamicSharedMemorySize, SMEM_BYTES);

    crf_kernel<<<NBLK, NTHR, SMEM_BYTES>>>(
        score, trans, startT, endT, v_label, role_label, out);
}